// round 5
// baseline (speedup 1.0000x reference)
#include <cuda_runtime.h>
#include <cuda_bf16.h>
#include <math.h>

#define BATCH   8
#define TT      2048
#define BT      16384      // BATCH*TT
#define DMODEL  1024
#define NP      512        // padded projection columns (450 real)
#define RECW2   784        // floats per (b,t) record: 6*128 vectors + 16 scalars
#define K1EXP   3072       // 3 * 1024  (bf16 split blocks: [hi, lo, hi])
#define K2EXP   384        // 12 * 32   (interleaved per-lane triplets)

// ---------------- device scratch (no allocations allowed) ----------------
__device__ __align__(16) __nv_bfloat16 g_Uexp[(size_t)BT * K1EXP];      // A for GEMM1
__device__ __align__(16) __nv_bfloat16 g_B1[(size_t)NP * K1EXP];        // B for GEMM1
__device__ __align__(16) __nv_bfloat16 g_B2[(size_t)DMODEL * K2EXP];    // B for GEMM2
__device__ __align__(16) __nv_bfloat16 g_Hexp[(size_t)BT * K2EXP];      // A for GEMM2
__device__ __align__(16) float g_Hraw[(size_t)BT * 128];                // raw scan output fp32
__device__ float g_P[(size_t)BT * NP];                                  // raw projections fp32
__device__ __align__(16) float g_rec2[(size_t)BT * RECW2];              // scan records
// record float4 layout (idx): [0,32) rot(S0,S1,D0,D1) per lane; [32,64) k1; [64,96) k2;
// [96,128) B; [128,160) m2_1 (SHIFTED: record t holds m2 of step t+2); [160,192) m2_2;
// [192..195] scalars: (b1,b2,cc,g11)(g12,g21,g22,p1)(p2,g'11,g'12,g'21)(g'22,p'1,p'2,pad)

// ---------------- helpers ----------------
__device__ __forceinline__ void split_bf16(float v, __nv_bfloat16& hi, __nv_bfloat16& lo)
{
    hi = __float2bfloat16(v);
    lo = __float2bfloat16(v - __bfloat162float(hi));
}

__device__ __forceinline__ unsigned pack2(__nv_bfloat16 a, __nv_bfloat16 b)
{
    __nv_bfloat162 p(a, b);
    return *(unsigned*)&p;
}

// Rt^T * v for the block rotation: z' = S(z + 0.1 y) ; y' = -D z + S y
__device__ __forceinline__ float4 rtx(float4 r, float4 v)
{
    float4 m;
    m.x = r.x * fmaf(0.1f, v.z, v.x);
    m.y = r.y * fmaf(0.1f, v.w, v.y);
    m.z = fmaf(-r.z, v.x, r.x * v.z);
    m.w = fmaf(-r.w, v.y, r.y * v.w);
    return m;
}

__device__ __forceinline__ float dot4(float4 a, float4 b)
{
    return fmaf(a.x, b.x, a.y * b.y) + fmaf(a.z, b.z, a.w * b.w);
}

// ---------------- U -> bf16 hi/lo expansion: Uexp[bt][3K] = [hi | lo | hi] ----------------
__global__ void conv_u(const float* __restrict__ u)
{
    size_t i = (size_t)blockIdx.x * 256 + threadIdx.x;
    size_t row = i >> 8;
    int c = (int)(i & 255) * 4;
    float4 v = *(const float4*)(u + row * DMODEL + c);
    __nv_bfloat16 h[4], l[4];
    split_bf16(v.x, h[0], l[0]); split_bf16(v.y, h[1], l[1]);
    split_bf16(v.z, h[2], l[2]); split_bf16(v.w, h[3], l[3]);
    __nv_bfloat16* base = g_Uexp + row * K1EXP;
    *(uint2*)(base + c)        = *(uint2*)h;
    *(uint2*)(base + 1024 + c) = *(uint2*)l;
    *(uint2*)(base + 2048 + c) = *(uint2*)h;
}

// ---------------- pack B1[n][3K]: blocks [Bh | Bh | Bl] ----------------
__global__ void pack_b1(const float* __restrict__ W_A, const float* __restrict__ W_k,
                        const float* __restrict__ W_beta, const float* __restrict__ B_w)
{
    int idx = blockIdx.x * 256 + threadIdx.x;
    if (idx >= NP * DMODEL) return;
    int n = idx >> 10, k = idx & 1023;
    float v = 0.f;
    if (n < 64)        v = W_A[n * DMODEL + k];
    else if (n < 320)  v = W_k[(size_t)(n - 64) * DMODEL + k];
    else if (n < 322)  v = W_beta[(n - 320) * DMODEL + k];
    else if (n < 450)  v = B_w[(size_t)(n - 322) * DMODEL + k];
    __nv_bfloat16 hi, lo; split_bf16(v, hi, lo);
    __nv_bfloat16* base = g_B1 + (size_t)n * K1EXP;
    base[k] = hi; base[1024 + k] = hi; base[2048 + k] = lo;
}

// ---------------- pack B2[d][384]: k = 12*l + 3*i + s ; (Ch,Ch,Cl), n=l+32i ------
__global__ void pack_b2(const float* __restrict__ C)
{
    int idx = blockIdx.x * 256 + threadIdx.x;
    if (idx >= DMODEL * 128) return;
    int d = idx >> 7, n = idx & 127;
    int l = n & 31, i = n >> 5;
    float v = C[(size_t)d * 128 + n];
    __nv_bfloat16 hi, lo; split_bf16(v, hi, lo);
    __nv_bfloat16* base = g_B2 + (size_t)d * K2EXP + 12 * l + 3 * i;
    base[0] = hi; base[1] = hi; base[2] = lo;
}

// ---------------- bf16 HMMA GEMM (unchanged from R4) ----------
template <int KTOT, int LDA, int LDB>
__global__ __launch_bounds__(256)
void mma_gemm(const __nv_bfloat16* __restrict__ A, const __nv_bfloat16* __restrict__ B,
              float* __restrict__ Cout, int ldc,
              const float* __restrict__ uPtr, const float* __restrict__ Dvec)
{
    __shared__ unsigned sA[2][128 * 16];
    __shared__ unsigned sB[2][128 * 16];

    const int tid  = threadIdx.x;
    const int m0   = blockIdx.y * 128;
    const int n0   = blockIdx.x * 128;
    const int lrow = tid >> 1, half = tid & 1;
    const int wid  = tid >> 5, lane = tid & 31;
    const int wm   = wid >> 1, wn = wid & 1;
    const int grp  = lane >> 2, tig = lane & 3;

    const uint4* Ag = (const uint4*)A + (size_t)(m0 + lrow) * (LDA / 8) + half * 2;
    const uint4* Bg = (const uint4*)B + (size_t)(n0 + lrow) * (LDB / 8) + half * 2;

    const int sw    = (lrow & 7) << 1;
    const int sbase = lrow * 16;
    const int w0    = half * 8;

    float acc[2][8][4];
#pragma unroll
    for (int im = 0; im < 2; im++)
#pragma unroll
        for (int in = 0; in < 8; in++)
#pragma unroll
            for (int q = 0; q < 4; q++) acc[im][in][q] = 0.f;

    constexpr int KIT = KTOT / 32;

    uint4 pa0 = Ag[0], pa1 = Ag[1], pb0 = Bg[0], pb1 = Bg[1];
    Ag += 4; Bg += 4;

#define STILE(dst, v0, v1)                                                              \
    do {                                                                                \
        ((uint2*)(dst))[(sbase + ((w0 + 0) ^ sw)) >> 1] = make_uint2((v0).x, (v0).y);   \
        ((uint2*)(dst))[(sbase + ((w0 + 2) ^ sw)) >> 1] = make_uint2((v0).z, (v0).w);   \
        ((uint2*)(dst))[(sbase + ((w0 + 4) ^ sw)) >> 1] = make_uint2((v1).x, (v1).y);   \
        ((uint2*)(dst))[(sbase + ((w0 + 6) ^ sw)) >> 1] = make_uint2((v1).z, (v1).w);   \
    } while (0)

    STILE(sA[0], pa0, pa1);
    STILE(sB[0], pb0, pb1);
    __syncthreads();

    for (int it = 0; it < KIT; it++) {
        const int cur = it & 1, nxt = cur ^ 1;
        if (it + 1 < KIT) {
            pa0 = Ag[0]; pa1 = Ag[1]; pb0 = Bg[0]; pb1 = Bg[1];
            Ag += 4; Bg += 4;
        }
        const unsigned* cA = sA[cur];
        const unsigned* cB = sB[cur];

#pragma unroll
        for (int kk = 0; kk < 2; kk++) {
            unsigned af[2][4], bf[8][2];
#pragma unroll
            for (int im = 0; im < 2; im++) {
                int r0 = wm * 32 + im * 16 + grp;
                int r1 = r0 + 8;
                int s0 = (r0 & 7) << 1;
                int s1 = (r1 & 7) << 1;
                af[im][0] = cA[r0 * 16 + ((kk * 8 + tig) ^ s0)];
                af[im][1] = cA[r1 * 16 + ((kk * 8 + tig) ^ s1)];
                af[im][2] = cA[r0 * 16 + ((kk * 8 + 4 + tig) ^ s0)];
                af[im][3] = cA[r1 * 16 + ((kk * 8 + 4 + tig) ^ s1)];
            }
#pragma unroll
            for (int in = 0; in < 8; in++) {
                int nr = wn * 64 + in * 8 + grp;
                int s  = (nr & 7) << 1;
                bf[in][0] = cB[nr * 16 + ((kk * 8 + tig) ^ s)];
                bf[in][1] = cB[nr * 16 + ((kk * 8 + 4 + tig) ^ s)];
            }
#pragma unroll
            for (int im = 0; im < 2; im++)
#pragma unroll
                for (int in = 0; in < 8; in++) {
                    float* c = acc[im][in];
                    asm volatile(
                        "mma.sync.aligned.m16n8k16.row.col.f32.bf16.bf16.f32 "
                        "{%0,%1,%2,%3}, {%4,%5,%6,%7}, {%8,%9}, {%0,%1,%2,%3};\n"
                        : "+f"(c[0]), "+f"(c[1]), "+f"(c[2]), "+f"(c[3])
                        : "r"(af[im][0]), "r"(af[im][1]), "r"(af[im][2]), "r"(af[im][3]),
                          "r"(bf[in][0]), "r"(bf[in][1]));
                }
        }

        if (it + 1 < KIT) {
            STILE(sA[nxt], pa0, pa1);
            STILE(sB[nxt], pb0, pb1);
            __syncthreads();
        }
    }
#undef STILE

#pragma unroll
    for (int im = 0; im < 2; im++) {
#pragma unroll
        for (int in = 0; in < 8; in++) {
            int row = m0 + wm * 32 + im * 16 + grp;
            int col = n0 + wn * 64 + in * 8 + tig * 2;
            float2 v01 = make_float2(acc[im][in][0], acc[im][in][1]);
            float2 v23 = make_float2(acc[im][in][2], acc[im][in][3]);
            if (uPtr) {
                size_t b0 = (size_t)row * ldc + col;
                size_t b1 = (size_t)(row + 8) * ldc + col;
                v01.x += uPtr[b0] * Dvec[col];
                v01.y += uPtr[b0 + 1] * Dvec[col + 1];
                v23.x += uPtr[b1] * Dvec[col];
                v23.y += uPtr[b1 + 1] * Dvec[col + 1];
            }
            *(float2*)(Cout + (size_t)row * ldc + col)       = v01;
            *(float2*)(Cout + (size_t)(row + 8) * ldc + col) = v23;
        }
    }
}

// ---------------- derive (pass 1): projections -> rot/k1/k2/B + beta/cc ----------------
__global__ void derive_kernel(const float* __restrict__ bA, const float* __restrict__ bk,
                              const float* __restrict__ bbeta, const float* __restrict__ Bb)
{
    const int bt = blockIdx.x;
    const int n = threadIdx.x;               // 0..127
    const int l = n & 31, i = n >> 5;
    const float* p = g_P + (size_t)bt * NP;
    float* rc = g_rec2 + (size_t)bt * RECW2;

    if (n < 64) {
        float a = fminf(fmaxf(p[n] + bA[n], 0.f), 100.f);
        float S = 1.f / (1.f + 0.01f * a);
        rc[4 * l + i]     = S;
        rc[4 * l + 2 + i] = 0.1f * a * S;    // DT*A*S
    }
    float k1 = p[64 + n]  + bk[n];
    float k2 = p[192 + n] + bk[128 + n];
    float Bv = p[322 + n] + Bb[n];

    float s1 = k1 * k1, s2 = k2 * k2, sx = k1 * k2;
#pragma unroll
    for (int off = 16; off; off >>= 1) {
        s1 += __shfl_xor_sync(0xffffffffu, s1, off);
        s2 += __shfl_xor_sync(0xffffffffu, s2, off);
        sx += __shfl_xor_sync(0xffffffffu, sx, off);
    }
    __shared__ float sm[12];
    __shared__ float bc[2];
    int w = n >> 5;
    if ((n & 31) == 0) { sm[w] = s1; sm[4 + w] = s2; sm[8 + w] = sx; }
    __syncthreads();
    if (n == 0) {
        float q1 = sm[0] + sm[1] + sm[2] + sm[3];
        float q2 = sm[4] + sm[5] + sm[6] + sm[7];
        float qx = sm[8] + sm[9] + sm[10] + sm[11];
        float i1 = 1.f / fmaxf(sqrtf(q1), 1e-12f);
        float i2 = 1.f / fmaxf(sqrtf(q2), 1e-12f);
        float be1 = 2.f / (1.f + expf(-(p[320] + bbeta[0])));
        float be2 = 2.f / (1.f + expf(-(p[321] + bbeta[1])));
        rc[768] = be1;
        rc[769] = be2;
        rc[770] = be1 * qx * i1 * i2;        // cc
        bc[0] = i1; bc[1] = i2;
    }
    __syncthreads();
    rc[128 + 4 * l + i] = k1 * bc[0];
    rc[256 + 4 * l + i] = k2 * bc[1];
    rc[384 + 4 * l + i] = Bv;
}

// ---------------- pass 2: lookahead vectors m2 + Gram scalars ----------------
// One warp per (b,t). Writes m2_{j,t} into record t-2 (shifted), scalars into record t.
__global__ void pass2_kernel()
{
    const int warp = threadIdx.x >> 5, lane = threadIdx.x & 31;
    const size_t bt = (size_t)blockIdx.x * 8 + warp;
    const int t = (int)(bt % TT);
    float4* rec = (float4*)g_rec2 + bt * (RECW2 / 4);
    const float4 Z = make_float4(0.f, 0.f, 0.f, 0.f);

    float4 rot = rec[lane];
    float4 k1  = rec[32 + lane], k2 = rec[64 + lane];
    const float4* rp1 = rec - (RECW2 / 4);
    const float4* rp2 = rec - 2 * (RECW2 / 4);
    float4 rotp = (t >= 1) ? rp1[lane] : Z;
    float4 k1p  = (t >= 1) ? rp1[32 + lane] : Z;
    float4 k2p  = (t >= 1) ? rp1[64 + lane] : Z;
    float4 Bp   = (t >= 1) ? rp1[96 + lane] : Z;
    float4 rotq = (t >= 2) ? rp2[lane] : Z;
    float4 k1q  = (t >= 2) ? rp2[32 + lane] : Z;
    float4 k2q  = (t >= 2) ? rp2[64 + lane] : Z;
    float4 Bq   = (t >= 2) ? rp2[96 + lane] : Z;

    float4 m01 = rtx(rot,  k1),  m02 = rtx(rot,  k2);
    float4 m11 = rtx(rotp, m01), m12 = rtx(rotp, m02);
    float4 m21 = rtx(rotq, m11), m22 = rtx(rotq, m12);

    float v[12];
    v[0]  = dot4(m01, k1p); v[1]  = dot4(m01, k2p);
    v[2]  = dot4(m02, k1p); v[3]  = dot4(m02, k2p);
    v[4]  = dot4(m01, Bp);  v[5]  = dot4(m02, Bp);
    v[6]  = dot4(m11, k1q); v[7]  = dot4(m11, k2q);
    v[8]  = dot4(m12, k1q); v[9]  = dot4(m12, k2q);
    v[10] = dot4(m11, Bq);  v[11] = dot4(m12, Bq);
#pragma unroll
    for (int off = 16; off; off >>= 1)
#pragma unroll
        for (int i = 0; i < 12; i++)
            v[i] += __shfl_xor_sync(0xffffffffu, v[i], off);

    if (t >= 2) {
        float4* rdst = (float4*)g_rec2 + (bt - 2) * (RECW2 / 4);
        rdst[128 + lane] = m21;
        rdst[160 + lane] = m22;
    }
    if (lane == 0) {
        float* rs = (float*)rec;
        rs[771] = v[0];  rs[772] = v[1];  rs[773] = v[2];  rs[774] = v[3];
        rs[775] = v[4];  rs[776] = v[5];
        rs[777] = v[6];  rs[778] = v[7];  rs[779] = v[8];  rs[780] = v[9];
        rs[781] = v[10]; rs[782] = v[11]; rs[783] = 0.f;
    }
}

// ---------------- scan: 2-step-lookahead pipelined recurrence, one warp per batch ---------
__global__ __launch_bounds__(32)
void scan_kernel()
{
    const int b = blockIdx.x, lane = threadIdx.x;
    const float4* __restrict__ r4 = (const float4*)g_rec2 + (size_t)b * TT * (RECW2 / 4);
    float* __restrict__ o = g_Hraw + (size_t)b * TT * 128;

    float h0 = 0.f, h1 = 0.f, h2 = 0.f, h3 = 0.f;
    float a1p = 0.f, a2p = 0.f, a1pp = 0.f, a2pp = 0.f;
    float e1s[2] = {0.f, 0.f}, e2s[2] = {0.f, 0.f};

    float4 scA[4], scB[4], scC[4], scD[4], m2a[4], m2b[4];  // depth-4 (record t)
    float4 rv[2], k1v[2], k2v[2], bvv[2];                   // depth-2 (record t)
#pragma unroll
    for (int p = 0; p < 4; p++) {
        const float4* rp = r4 + (size_t)p * (RECW2 / 4);
        m2a[p] = rp[128 + lane]; m2b[p] = rp[160 + lane];
        scA[p] = rp[192]; scB[p] = rp[193]; scC[p] = rp[194]; scD[p] = rp[195];
    }
#pragma unroll
    for (int p = 0; p < 2; p++) {
        const float4* rp = r4 + (size_t)p * (RECW2 / 4);
        rv[p]  = rp[lane];       k1v[p] = rp[32 + lane];
        k2v[p] = rp[64 + lane];  bvv[p] = rp[96 + lane];
    }

#pragma unroll 4
    for (int t = 0; t < TT; t++) {
        const int sd = t & 3, ss = t & 1;
        const float4 s0 = scA[sd], s1 = scB[sd], s2 = scC[sd], s3 = scD[sd];
        const float4 ma = m2a[sd], mb = m2b[sd];
        const float4 R  = rv[ss],  K1 = k1v[ss], K2 = k2v[ss], Bv = bvv[ss];

        // refills (consumed values already copied to locals)
        if (t + 4 < TT) {
            const float4* rp = r4 + (size_t)(t + 4) * (RECW2 / 4);
            m2a[sd] = rp[128 + lane]; m2b[sd] = rp[160 + lane];
            scA[sd] = rp[192]; scB[sd] = rp[193]; scC[sd] = rp[194]; scD[sd] = rp[195];
        }
        if (t + 2 < TT) {
            const float4* rp = r4 + (size_t)(t + 2) * (RECW2 / 4);
            rv[ss]  = rp[lane];      k1v[ss] = rp[32 + lane];
            k2v[ss] = rp[64 + lane]; bvv[ss] = rp[96 + lane];
        }

        // D combine: e (butterfly vs h_{t-3}) + Gram-scalar corrections
        float D1 = e1s[ss] + (s1.w + s3.y);
        D1 = fmaf(-a1p,  s0.w, D1); D1 = fmaf(-a2p,  s1.x, D1);
        D1 = fmaf(-a1pp, s2.y, D1); D1 = fmaf(-a2pp, s2.z, D1);
        float D2 = e2s[ss] + (s2.x + s3.z);
        D2 = fmaf(-a1p,  s1.y, D2); D2 = fmaf(-a2p,  s1.z, D2);
        D2 = fmaf(-a1pp, s2.w, D2); D2 = fmaf(-a2pp, s3.x, D2);
        float a1 = s0.x * D1;
        float a2 = s0.y * fmaf(-s0.z, D1, D2);
        a1pp = a1p; a2pp = a2p; a1p = a1; a2p = a2;

        // partial dots for step t+2 against h_{t-1} (current h), then butterfly
        float q1 = fmaf(ma.x, h0, ma.y * h1) + fmaf(ma.z, h2, ma.w * h3);
        float q2 = fmaf(mb.x, h0, mb.y * h1) + fmaf(mb.z, h2, mb.w * h3);
#pragma unroll
        for (int off = 16; off; off >>= 1) {
            q1 += __shfl_xor_sync(0xffffffffu, q1, off);
            q2 += __shfl_xor_sync(0xffffffffu, q2, off);
        }
        e1s[ss] = q1; e2s[ss] = q2;

        // rotate + rank-2 update + bias
        float w0 = fmaf(-R.z, h2, R.x * h0);
        float w1 = fmaf(-R.w, h3, R.y * h1);
        float w2 = R.x * fmaf(0.1f, h0, h2);
        float w3 = R.y * fmaf(0.1f, h1, h3);
        h0 = fmaf(-a2, K2.x, fmaf(-a1, K1.x, w0 + Bv.x));
        h1 = fmaf(-a2, K2.y, fmaf(-a1, K1.y, w1 + Bv.y));
        h2 = fmaf(-a2, K2.z, fmaf(-a1, K1.z, w2 + Bv.z));
        h3 = fmaf(-a2, K2.w, fmaf(-a1, K1.w, w3 + Bv.w));

        *((float4*)(o + (size_t)t * 128) + lane) = make_float4(h0, h1, h2, h3);
    }
}

// ---------------- conv_h: raw fp32 h -> bf16 hi/lo triplets for GEMM2 ----------------
__global__ void conv_h()
{
    int idx = blockIdx.x * 256 + threadIdx.x;   // BT*32
    int bt = idx >> 5, l = idx & 5 * 6 + 1;     // (idx & 31)
    l = idx & 31;
    float4 hv = *((const float4*)g_Hraw + (size_t)bt * 32 + l);
    __nv_bfloat16 h[4], lo[4];
    split_bf16(hv.x, h[0], lo[0]); split_bf16(hv.y, h[1], lo[1]);
    split_bf16(hv.z, h[2], lo[2]); split_bf16(hv.w, h[3], lo[3]);
    unsigned w0 = pack2(h[0], lo[0]);
    unsigned w1 = pack2(h[0], h[1]);
    unsigned w2 = pack2(lo[1], h[1]);
    unsigned w3 = pack2(h[2], lo[2]);
    unsigned w4 = pack2(h[2], h[3]);
    unsigned w5 = pack2(lo[3], h[3]);
    uint2* op = (uint2*)(g_Hexp + (size_t)bt * K2EXP) + 3 * l;
    op[0] = make_uint2(w0, w1);
    op[1] = make_uint2(w2, w3);
    op[2] = make_uint2(w4, w5);
}

// ---------------- launch ----------------
extern "C" void kernel_launch(void* const* d_in, const int* in_sizes, int n_in,
                              void* d_out, int out_size)
{
    const float* u      = (const float*)d_in[0];
    const float* W_A    = (const float*)d_in[1];
    const float* b_A    = (const float*)d_in[2];
    const float* W_k    = (const float*)d_in[3];
    const float* b_k    = (const float*)d_in[4];
    const float* W_beta = (const float*)d_in[5];
    const float* b_beta = (const float*)d_in[6];
    const float* B_w    = (const float*)d_in[7];
    const float* B_b    = (const float*)d_in[8];
    const float* C      = (const float*)d_in[9];
    const float* D      = (const float*)d_in[10];
    float* out = (float*)d_out;

    pack_b1<<<(NP * DMODEL + 255) / 256, 256>>>(W_A, W_k, W_beta, B_w);
    pack_b2<<<(DMODEL * 128 + 255) / 256, 256>>>(C);
    conv_u<<<(BT * (DMODEL / 4)) / 256, 256>>>(u);

    // GEMM1: P[16384 x 512] = Uexp[16384 x 3072] * B1^T
    {
        __nv_bfloat16 *dA, *dB; float* dP;
        cudaGetSymbolAddress((void**)&dA, g_Uexp);
        cudaGetSymbolAddress((void**)&dB, g_B1);
        cudaGetSymbolAddress((void**)&dP, g_P);
        mma_gemm<K1EXP, K1EXP, K1EXP><<<dim3(NP / 128, BT / 128), 256>>>(
            dA, dB, dP, NP, nullptr, nullptr);
    }

    derive_kernel<<<BT, 128>>>(b_A, b_k, b_beta, B_b);
    pass2_kernel<<<BT / 8, 256>>>();

    scan_kernel<<<BATCH, 32>>>();
    conv_h<<<(BT * 32) / 256, 256>>>();

    // GEMM2: out[16384 x 1024] = Hexp[16384 x 384] * B2^T + u * D
    {
        __nv_bfloat16 *dA, *dB;
        cudaGetSymbolAddress((void**)&dA, g_Hexp);
        cudaGetSymbolAddress((void**)&dB, g_B2);
        mma_gemm<K2EXP, K2EXP, K2EXP><<<dim3(DMODEL / 128, BT / 128), 256>>>(
            dA, dB, out, DMODEL, u, D);
    }
}